// round 1
// baseline (speedup 1.0000x reference)
#include <cuda_runtime.h>
#include <cstdint>

#define B_  4
#define C_  256
#define H_  96
#define W_  128
#define P_  9

#define TX  32          // x pixels per block
#define TY  4           // y pixels per block
#define PT  4           // x pixels per thread
#define XG  (TX / PT)   // 8 x-groups
#define THREADS (XG * P_ * TY)   // 288
#define CC  8           // channels per stage
#define NSTAGE (C_ / CC)         // 32
#define HALO_W (TX + 8) // 40
#define HALO_H (TY + 8) // 12

#define S1_BUF_FLOATS (CC * TY * TX)           // 1024
#define S2_BUF_FLOATS (CC * HALO_H * HALO_W)   // 3840
#define S1_BUF_BYTES  (S1_BUF_FLOATS * 4)      // 4096
#define S2_BUF_BYTES  (S2_BUF_FLOATS * 4)      // 15360

// number of float4 loads per stage
#define N_LD1 (CC * TY * (TX / 4))             // 256
#define N_LD2 (CC * HALO_H * (HALO_W / 4))     // 960
#define N_LD  (N_LD1 + N_LD2)                  // 1216
#define LD_PER_THREAD 5                        // ceil(1216/288)

__device__ __forceinline__ void cp_async16(uint32_t dst, const void* src, int srcsize) {
    asm volatile("cp.async.cg.shared.global [%0], [%1], 16, %2;\n"
                 :: "r"(dst), "l"(src), "r"(srcsize));
}
__device__ __forceinline__ void cp_commit() {
    asm volatile("cp.async.commit_group;\n" ::: "memory");
}
template <int N>
__device__ __forceinline__ void cp_wait() {
    asm volatile("cp.async.wait_group %0;\n" :: "n"(N) : "memory");
}

__global__ void __launch_bounds__(THREADS, 2)
corr_kernel(const float* __restrict__ in1,
            const float* __restrict__ in2,
            float* __restrict__ out)
{
    __shared__ __align__(16) float s1[2][CC][TY][TX];          // in1 tile
    __shared__ __align__(16) float s2[2][CC][HALO_H][HALO_W];  // in2 halo

    const int tid = threadIdx.x;
    const int b   = blockIdx.z;
    const int y0  = blockIdx.y * TY;
    const int x0  = blockIdx.x * TX;

    const float* g1 = in1 + (size_t)b * C_ * H_ * W_;
    const float* g2 = in2 + (size_t)b * C_ * H_ * W_;

    const uint32_t s1base = (uint32_t)__cvta_generic_to_shared(&s1[0][0][0][0]);
    const uint32_t s2base = (uint32_t)__cvta_generic_to_shared(&s2[0][0][0][0]);

    // ---- precompute per-thread load descriptors (stage 0, buffer 0) ----
    uint32_t     l_soff[LD_PER_THREAD];
    const float* l_gptr[LD_PER_THREAD];
    int          l_sz  [LD_PER_THREAD];
    uint32_t     l_bstr[LD_PER_THREAD];

    #pragma unroll
    for (int k = 0; k < LD_PER_THREAD; k++) {
        int idx = tid + k * THREADS;
        if (idx < N_LD1) {
            // in1 tile: 32 float4 per channel (4 rows x 8 chunks)
            int cc = idx >> 5;
            int r  = idx & 31;
            int yy = r >> 3;
            int j  = r & 7;
            l_soff[k] = s1base + (uint32_t)(((cc * TY + yy) * TX + j * 4) * 4);
            l_gptr[k] = g1 + ((size_t)cc * H_ + (y0 + yy)) * W_ + x0 + 4 * j;
            l_sz[k]   = 16;
            l_bstr[k] = S1_BUF_BYTES;
        } else if (idx < N_LD) {
            // in2 halo: 120 float4 per channel (12 rows x 10 chunks)
            int id2 = idx - N_LD1;
            int cc  = id2 / 120;
            int r   = id2 - cc * 120;
            int ry  = r / 10;
            int j   = r - ry * 10;
            int gy  = y0 + ry - 4;
            int gx  = x0 + 4 * j - 4;
            bool inb = (gy >= 0) && (gy < H_) && (gx >= 0) && (gx <= W_ - 4);
            l_soff[k] = s2base + (uint32_t)(((cc * HALO_H + ry) * HALO_W + j * 4) * 4);
            l_gptr[k] = inb ? (g2 + ((size_t)cc * H_ + gy) * W_ + gx) : g2;
            l_sz[k]   = inb ? 16 : 0;   // src-size 0 => zero-fill
            l_bstr[k] = S2_BUF_BYTES;
        } else {
            l_sz[k]   = -1;
            l_soff[k] = 0;
            l_gptr[k] = g1;
            l_bstr[k] = 0;
        }
    }

    // ---- compute-role decomposition ----
    const int g   = tid & 7;          // x-group (0..7)
    const int dy  = (tid >> 3) % 9;   // shift row (0..8)
    const int yy  = tid / 72;         // block-local output row (0..3)

    float acc[PT][P_];
    #pragma unroll
    for (int t = 0; t < PT; t++)
        #pragma unroll
        for (int d = 0; d < P_; d++)
            acc[t][d] = 0.0f;

    const float* w_base = &s2[0][0][yy + dy][4 * g];  // 12-float window start
    const float* a_base = &s1[0][0][yy][4 * g];       // 4-float in1 start

    // ---- prologue: issue stage 0 ----
    {
        const size_t goff = 0;
        #pragma unroll
        for (int k = 0; k < LD_PER_THREAD; k++)
            if (l_sz[k] >= 0)
                cp_async16(l_soff[k], l_gptr[k] + goff, l_sz[k]);
        cp_commit();
    }

    for (int st = 0; st < NSTAGE; st++) {
        if (st + 1 < NSTAGE) {
            const int    buf  = (st + 1) & 1;
            const size_t goff = (size_t)(st + 1) * CC * H_ * W_;
            #pragma unroll
            for (int k = 0; k < LD_PER_THREAD; k++)
                if (l_sz[k] >= 0)
                    cp_async16(l_soff[k] + buf * l_bstr[k], l_gptr[k] + goff, l_sz[k]);
            cp_commit();
            cp_wait<1>();   // stage st landed, stage st+1 in flight
        } else {
            cp_wait<0>();
        }
        __syncthreads();

        const int buf = st & 1;
        const float* wp = w_base + buf * S2_BUF_FLOATS;
        const float* ap = a_base + buf * S1_BUF_FLOATS;

        #pragma unroll
        for (int cc = 0; cc < CC; cc++) {
            float4 w0 = *reinterpret_cast<const float4*>(wp);
            float4 w1 = *reinterpret_cast<const float4*>(wp + 4);
            float4 w2 = *reinterpret_cast<const float4*>(wp + 8);
            float4 a  = *reinterpret_cast<const float4*>(ap);

            float wf[12];
            wf[0] = w0.x; wf[1]  = w0.y; wf[2]  = w0.z; wf[3]  = w0.w;
            wf[4] = w1.x; wf[5]  = w1.y; wf[6]  = w1.z; wf[7]  = w1.w;
            wf[8] = w2.x; wf[9]  = w2.y; wf[10] = w2.z; wf[11] = w2.w;

            float av[PT];
            av[0] = a.x; av[1] = a.y; av[2] = a.z; av[3] = a.w;

            #pragma unroll
            for (int t = 0; t < PT; t++)
                #pragma unroll
                for (int d = 0; d < P_; d++)
                    acc[t][d] = fmaf(av[t], wf[t + d], acc[t][d]);

            wp += HALO_H * HALO_W;
            ap += TY * TX;
        }
        __syncthreads();
    }

    // ---- write output: out[b][dy][dx][y0+yy][x0+4g .. +3] ----
    {
        const size_t hw = (size_t)H_ * W_;
        float* obase = out + (((size_t)b * P_ + dy) * P_) * hw
                     + (size_t)(y0 + yy) * W_ + x0 + 4 * g;
        #pragma unroll
        for (int d = 0; d < P_; d++) {
            float4 v;
            v.x = acc[0][d];
            v.y = acc[1][d];
            v.z = acc[2][d];
            v.w = acc[3][d];
            *reinterpret_cast<float4*>(obase + (size_t)d * hw) = v;
        }
    }
}

extern "C" void kernel_launch(void* const* d_in, const int* in_sizes, int n_in,
                              void* d_out, int out_size) {
    const float* in1 = (const float*)d_in[0];
    const float* in2 = (const float*)d_in[1];
    float* out = (float*)d_out;

    dim3 grid(W_ / TX, H_ / TY, B_);   // (4, 24, 4) = 384 blocks
    dim3 block(THREADS);               // 288
    corr_kernel<<<grid, block>>>(in1, in2, out);
}